// round 14
// baseline (speedup 1.0000x reference)
#include <cuda_runtime.h>
#include <cuda_fp16.h>

#define B_  32
#define C_  256
#define T_  2048
#define K_  1024
#define N_  (B_ * T_)        // 65536
#define STT 64
#define OUTQ_ELEMS ((size_t)B_ * C_ * T_)

#define EPS 2.0e-3f
#define TWO_POW_M9 0.001953125f   // exact 2^-9

// device scratch (static — no allocation)
__device__ float    g_cnorm[K_];
__device__ float    g_sx[N_];
__device__ __half   g_A[(size_t)N_ * 256];    // x0 = rn16(x), 32MB
__device__ float    g_xr[(size_t)N_ * 256];   // exact fp32 x rows, 64MB
__device__ __half   g_B[(size_t)K_ * 256];    // c0 = rn16(c * 2^10)
__device__ float    g_tbv[4 * N_];            // per-(ntile, point) approx best
__device__ unsigned g_mask[(size_t)4 * N_ * 8]; // 256-bit candidate masks
__device__ int      g_idx[N_];
__device__ int      g_queue[N_];
__device__ int      g_nq;
__device__ int      g_qhead;
__device__ int      g_done;
__device__ double   g_sum;

// ---------------- helpers ----------------
__device__ __forceinline__ unsigned smem_u32(const void* p) {
    unsigned r;
    asm("{ .reg .u64 t; cvta.to.shared.u64 t, %1; cvt.u32.u64 %0, t; }"
        : "=r"(r) : "l"(p));
    return r;
}
__device__ __forceinline__ void cp16(unsigned dst, const void* src) {
    asm volatile("cp.async.cg.shared.global [%0], [%1], 16;" :: "r"(dst), "l"(src));
}
__device__ __forceinline__ void mma16816(float* d, const unsigned* a, const unsigned* b) {
    asm volatile("mma.sync.aligned.m16n8k16.row.col.f32.f16.f16.f32 "
        "{%0,%1,%2,%3}, {%4,%5,%6,%7}, {%8,%9}, {%0,%1,%2,%3};"
        : "+f"(d[0]), "+f"(d[1]), "+f"(d[2]), "+f"(d[3])
        : "r"(a[0]), "r"(a[1]), "r"(a[2]), "r"(a[3]), "r"(b[0]), "r"(b[1]));
}

// ---------------------------------------------------------------------------
// Prep ALL: blocks 0..15 -> codebook (norms + fp16 pack); blocks 16..527 -> X.
// ---------------------------------------------------------------------------
__global__ __launch_bounds__(256)
void vq_prep_all(const float* __restrict__ in, const float* __restrict__ cb) {
    extern __shared__ float tile[];
    const int tid = threadIdx.x;

    if (blockIdx.x < 16) {
        const int k0 = blockIdx.x * 64;
        if (blockIdx.x == 0 && tid == 0) {
            g_sum = 0.0; g_nq = 0; g_qhead = 0; g_done = 0;
        }
        for (int i = tid; i < 4096; i += 256) {
            int row = i >> 6, c4 = i & 63;
            *(float4*)&tile[row * 260 + c4 * 4] =
                __ldg((const float4*)(cb + (size_t)(k0 + row) * 256) + c4);
        }
        __syncthreads();

        if (tid < 64) {
            const float* r = &tile[tid * 260];
            float s = 0.0f;
            for (int d = 0; d < 256; ++d)
                s = __fadd_rn(s, __fmul_rn(r[d], r[d]));
            g_cnorm[k0 + tid] = s;
        }

        for (int i = tid; i < 2048; i += 256) {
            int row = i >> 5, g = i & 31;
            const float* src = &tile[row * 260 + g * 8];
            __half h[8];
#pragma unroll
            for (int j = 0; j < 8; ++j) h[j] = __float2half_rn(src[j] * 1024.0f);
            *(uint4*)(g_B + (size_t)(k0 + row) * 256 + g * 8) = *(uint4*)h;
        }
        return;
    }

    const int xb = blockIdx.x - 16;
    const int b = xb >> 4, t0 = (xb & 15) * 128;
    float s = 0.0f;

    for (int ch = 0; ch < 4; ++ch) {
        for (int i = tid; i < 2048; i += 256) {
            int d = i >> 5, q = i & 31;
            float4 v = __ldg((const float4*)(
                in + ((size_t)b * C_ + ch * 64 + d) * T_ + t0 + q * 4));
            *(float4*)&tile[d * 132 + q * 4] = v;
        }
        __syncthreads();

        if (tid < 128) {
#pragma unroll 8
            for (int dl = 0; dl < 64; ++dl) {
                float v = tile[dl * 132 + tid];
                s = __fadd_rn(s, __fmul_rn(v, v));
            }
        }

        for (int i = tid; i < 2048; i += 256) {
            int row = i >> 4, g = i & 15;
            float f0 = tile[(g * 4 + 0) * 132 + row];
            float f1 = tile[(g * 4 + 1) * 132 + row];
            float f2 = tile[(g * 4 + 2) * 132 + row];
            float f3 = tile[(g * 4 + 3) * 132 + row];
            const size_t p = (size_t)b * T_ + t0 + row;
            *(float4*)(g_xr + p * 256 + ch * 64 + g * 4) =
                make_float4(f0, f1, f2, f3);
            __half h[4] = { __float2half_rn(f0), __float2half_rn(f1),
                            __float2half_rn(f2), __float2half_rn(f3) };
            *(uint2*)(g_A + p * 256 + ch * 64 + g * 4) = *(uint2*)h;
        }
        __syncthreads();
    }
    if (tid < 128) g_sx[(size_t)b * T_ + t0 + tid] = s;
}

// ---------------------------------------------------------------------------
// GEMM + candidate-mask. 128t x 256n x K256. 512 threads / 16 warps,
// warp tile 64x32 (64 acc regs -> 128 regs/thread), 2-stage pipeline,
// 106KB smem -> 2 CTAs/SM (32 warps/SM) for latency hiding.
// ---------------------------------------------------------------------------
#define SMEM_AS 0          // 2 x 16384 = 32768
#define SMEM_BS 32768      // 2 x 32768 -> ends 98304
#define SMEM_CN 98304      // 1024
#define SMEM_SX 99328      // 512
#define SMEM_RV 99840      // [128][8] float = 4096
#define SMEM_MK 103936     // [128][8] u32  = 4096
#define SMEM_BT 108032     // 512
#define SMEM_G  108544

__device__ __forceinline__ void load_chunk(unsigned as0, unsigned bs0, int stage,
                                           size_t aRowBase, int n0, int c, int tid) {
    unsigned abase = as0 + stage * 16384;
    const __half* asrc = g_A + aRowBase + c * 64;
    for (int i = tid; i < 1024; i += 512) {
        int r = i >> 3, g = i & 7;
        cp16(abase + r * 128 + ((g ^ (r & 7)) << 4), asrc + (size_t)r * 256 + g * 8);
    }
    unsigned bbase = bs0 + stage * 32768;
    const __half* bsrc = g_B + (size_t)n0 * 256 + c * 64;
    for (int i = tid; i < 2048; i += 512) {
        int r = i >> 3, g = i & 7;
        cp16(bbase + r * 128 + ((g ^ (r & 7)) << 4), bsrc + (size_t)r * 256 + g * 8);
    }
}

__global__ __launch_bounds__(512, 2)
void vq_gemm_kernel() {
    extern __shared__ char smem[];
    unsigned sb  = smem_u32(smem);
    unsigned as0 = sb + SMEM_AS, bs0 = sb + SMEM_BS;
    float*    cn_s   = (float*)(smem + SMEM_CN);
    float*    sx_s   = (float*)(smem + SMEM_SX);
    float*    red_v  = (float*)(smem + SMEM_RV);   // [128][8]
    unsigned* mask_s = (unsigned*)(smem + SMEM_MK);
    float*    best_s = (float*)(smem + SMEM_BT);

    const int tid  = threadIdx.x;
    const int lane = tid & 31, wid = tid >> 5;
    const int wm = wid >> 3, wn = wid & 7;     // 2 x 8 warp grid, 64x32 tiles
    const int tTile = blockIdx.x >> 2, nTile = blockIdx.x & 3;
    const int gt0 = tTile * 128, n0 = nTile * 256;
    const size_t aRowBase = (size_t)gt0 * 256;

    load_chunk(as0, bs0, 0, aRowBase, n0, 0, tid);
    asm volatile("cp.async.commit_group;");
    load_chunk(as0, bs0, 1, aRowBase, n0, 1, tid);
    asm volatile("cp.async.commit_group;");

    if (tid < 128) sx_s[tid] = g_sx[gt0 + tid];
    if (tid < 256) cn_s[tid] = g_cnorm[n0 + tid];

    float acc[4][4][4];
#pragma unroll
    for (int m = 0; m < 4; ++m)
#pragma unroll
        for (int n = 0; n < 4; ++n)
#pragma unroll
            for (int j = 0; j < 4; ++j) acc[m][n][j] = 0.0f;

#pragma unroll
    for (int c = 0; c < 4; ++c) {
        if (c < 3) { asm volatile("cp.async.wait_group 1;"); }
        else       { asm volatile("cp.async.wait_group 0;"); }
        __syncthreads();
        const int stage = c & 1;
        const unsigned abase = as0 + stage * 16384;
        const unsigned bbase = bs0 + stage * 32768;

#pragma unroll
        for (int kk = 0; kk < 4; ++kk) {
            unsigned a_frag[4][4], b_frag[4][2];
#pragma unroll
            for (int m = 0; m < 4; ++m) {
                int trow = wm * 64 + m * 16 + (lane & 15);
                int g = (kk << 1) + (lane >> 4);
                unsigned addr = abase + trow * 128 + ((g ^ (lane & 7)) << 4);
                asm volatile("ldmatrix.sync.aligned.m8n8.x4.shared.b16 {%0,%1,%2,%3}, [%4];"
                    : "=r"(a_frag[m][0]), "=r"(a_frag[m][1]),
                      "=r"(a_frag[m][2]), "=r"(a_frag[m][3]) : "r"(addr));
            }
#pragma unroll
            for (int n2 = 0; n2 < 2; ++n2) {
                int nrow = wn * 32 + n2 * 16 + ((lane >> 4) & 1) * 8 + (lane & 7);
                int g = (kk << 1) + ((lane >> 3) & 1);
                unsigned addr = bbase + nrow * 128 + ((g ^ (lane & 7)) << 4);
                asm volatile("ldmatrix.sync.aligned.m8n8.x4.shared.b16 {%0,%1,%2,%3}, [%4];"
                    : "=r"(b_frag[n2 * 2][0]),     "=r"(b_frag[n2 * 2][1]),
                      "=r"(b_frag[n2 * 2 + 1][0]), "=r"(b_frag[n2 * 2 + 1][1])
                    : "r"(addr));
            }
#pragma unroll
            for (int m = 0; m < 4; ++m)
#pragma unroll
                for (int n = 0; n < 4; ++n)
                    mma16816(acc[m][n], a_frag[m], b_frag[n]);
        }

        __syncthreads();   // everyone done reading stage (c&1) before refill
        if (c + 2 < 4) load_chunk(as0, bs0, c & 1, aRowBase, n0, c + 2, tid);
        asm volatile("cp.async.commit_group;");
    }

    // Pass 1: per-t tile-best
#pragma unroll
    for (int m = 0; m < 4; ++m) {
        const int ra = wm * 64 + m * 16 + (lane >> 2);
        const int rb = ra + 8;
        const float sxa = sx_s[ra], sxb = sx_s[rb];
        float va = 3.4e38f, vb = 3.4e38f;
#pragma unroll
        for (int n = 0; n < 4; ++n) {
            const int kc = wn * 32 + n * 8 + ((lane & 3) << 1);
            const float sc0 = cn_s[kc], sc1 = cn_s[kc + 1];
            const float* d = acc[m][n];
            va = fminf(va, __fsub_rn(__fadd_rn(sxa, sc0), __fmul_rn(d[0], TWO_POW_M9)));
            va = fminf(va, __fsub_rn(__fadd_rn(sxa, sc1), __fmul_rn(d[1], TWO_POW_M9)));
            vb = fminf(vb, __fsub_rn(__fadd_rn(sxb, sc0), __fmul_rn(d[2], TWO_POW_M9)));
            vb = fminf(vb, __fsub_rn(__fadd_rn(sxb, sc1), __fmul_rn(d[3], TWO_POW_M9)));
        }
#pragma unroll
        for (int s = 1; s <= 2; s <<= 1) {
            va = fminf(va, __shfl_xor_sync(0xffffffffu, va, s));
            vb = fminf(vb, __shfl_xor_sync(0xffffffffu, vb, s));
        }
        if ((lane & 3) == 0) {
            red_v[ra * 8 + wn] = va;
            red_v[rb * 8 + wn] = vb;
        }
    }
    __syncthreads();
    if (tid < 128) {
        float bv = red_v[tid * 8];
#pragma unroll
        for (int w = 1; w < 8; ++w) bv = fminf(bv, red_v[tid * 8 + w]);
        best_s[tid] = bv;
    }
    __syncthreads();

    // Pass 2: candidate bits, ballot-free lane-group OR (warp wn owns word wn)
#pragma unroll
    for (int m = 0; m < 4; ++m) {
        const int ra = wm * 64 + m * 16 + (lane >> 2);
        const int rb = ra + 8;
        const float sxa = sx_s[ra], sxb = sx_s[rb];
        const float tha = best_s[ra] + EPS, thb = best_s[rb] + EPS;
        unsigned lma = 0u, lmb = 0u;
#pragma unroll
        for (int n = 0; n < 4; ++n) {
            const int bitp = n * 8 + ((lane & 3) << 1);
            const int kc = wn * 32 + bitp;
            const float sc0 = cn_s[kc], sc1 = cn_s[kc + 1];
            const float* d = acc[m][n];
            if (__fsub_rn(__fadd_rn(sxa, sc0), __fmul_rn(d[0], TWO_POW_M9)) <= tha)
                lma |= 1u << bitp;
            if (__fsub_rn(__fadd_rn(sxa, sc1), __fmul_rn(d[1], TWO_POW_M9)) <= tha)
                lma |= 1u << (bitp + 1);
            if (__fsub_rn(__fadd_rn(sxb, sc0), __fmul_rn(d[2], TWO_POW_M9)) <= thb)
                lmb |= 1u << bitp;
            if (__fsub_rn(__fadd_rn(sxb, sc1), __fmul_rn(d[3], TWO_POW_M9)) <= thb)
                lmb |= 1u << (bitp + 1);
        }
        lma |= __shfl_xor_sync(0xffffffffu, lma, 1);
        lma |= __shfl_xor_sync(0xffffffffu, lma, 2);
        lmb |= __shfl_xor_sync(0xffffffffu, lmb, 1);
        lmb |= __shfl_xor_sync(0xffffffffu, lmb, 2);
        if ((lane & 3) == 0) {
            mask_s[ra * 8 + wn] = lma;
            mask_s[rb * 8 + wn] = lmb;
        }
    }
    __syncthreads();

    if (tid < 128) g_tbv[nTile * N_ + gt0 + tid] = best_s[tid];
    for (int i = tid; i < 1024; i += 512) {
        int t = i >> 3, w = i & 7;
        g_mask[((size_t)nTile * N_ + gt0 + t) * 8 + w] = mask_s[t * 8 + w];
    }
}

// ---------------------------------------------------------------------------
// Classify: single-candidate points resolved inline; rest -> global queue.
// ---------------------------------------------------------------------------
__global__ __launch_bounds__(256)
void vq_classify_kernel(float* __restrict__ out_idx_f) {
    const int p = blockIdx.x * 256 + threadIdx.x;
    float tb0 = g_tbv[p],           tb1 = g_tbv[N_ + p];
    float tb2 = g_tbv[2 * N_ + p],  tb3 = g_tbv[3 * N_ + p];
    const float thr = fminf(fminf(tb0, tb1), fminf(tb2, tb3)) + EPS;

    int nc = 0, firstk = -1;
#pragma unroll
    for (int i = 0; i < 4; ++i) {
        float tbi = (i == 0) ? tb0 : (i == 1) ? tb1 : (i == 2) ? tb2 : tb3;
        if (tbi <= thr) {
#pragma unroll
            for (int w = 0; w < 8; ++w) {
                unsigned m = g_mask[((size_t)i * N_ + p) * 8 + w];
                if (m) {
                    if (firstk < 0) firstk = i * 256 + w * 32 + (__ffs(m) - 1);
                    nc += __popc(m);
                }
            }
        }
    }
    if (nc == 1) {
        g_idx[p] = firstk;
        out_idx_f[p] = (float)firstk;
    } else {
        int pos = atomicAdd(&g_nq, 1);
        g_queue[pos] = p;
    }
}

// ---------------------------------------------------------------------------
// Exact refine: one warp per queued point, global work-stealing queue.
// ---------------------------------------------------------------------------
#define RW 8
__global__ __launch_bounds__(RW * 32)
void vq_refine_kernel(const float* __restrict__ cb,
                      float* __restrict__ out_idx_f) {
    __shared__ float xbuf[RW][256];
    __shared__ int   cand[RW][128];
    __shared__ int   qpos[RW];

    const int lane = threadIdx.x & 31;
    const int wid  = threadIdx.x >> 5;
    const unsigned FULL = 0xffffffffu;
    const int total = g_nq;

    for (;;) {
        if (lane == 0) qpos[wid] = atomicAdd(&g_qhead, 1);
        __syncwarp();
        const int qp = qpos[wid];
        if (qp >= total) break;
        const int p = g_queue[qp];

        float tbl = (lane < 4) ? g_tbv[lane * N_ + p] : 3.4e38f;
        float gb = tbl;
#pragma unroll
        for (int s = 1; s < 4; s <<= 1)
            gb = fminf(gb, __shfl_xor_sync(FULL, gb, s));
        gb = __shfl_sync(FULL, gb, 0);
        const float thr = gb + EPS;

        const int ti = lane >> 3;
        float tbi = __shfl_sync(FULL, tbl, ti);
        unsigned m = 0;
        if (tbi <= thr) m = g_mask[((size_t)ti * N_ + p) * 8 + (lane & 7)];
        int cnt = __popc(m);
        int pre = cnt;
#pragma unroll
        for (int s = 1; s < 32; s <<= 1) {
            int v = __shfl_up_sync(FULL, pre, s);
            if (lane >= s) pre += v;
        }
        int nc = __shfl_sync(FULL, pre, 31);
        if (nc > 128) nc = 128;
        int excl = pre - cnt;
        unsigned mm = m;
        while (mm && excl < 128) {
            int bpos = __ffs(mm) - 1;
            mm &= mm - 1;
            cand[wid][excl++] = lane * 32 + bpos;
        }

        {
            const float4* src = (const float4*)(g_xr + (size_t)p * 256);
            float4* dst = (float4*)xbuf[wid];
            dst[lane]      = src[lane];
            dst[lane + 32] = src[lane + 32];
        }
        __syncwarp();

        const float sx = g_sx[p];
        float bv = 3.4e38f;
        int   bk = 0x7fffffff;
        for (int j = lane; j < nc; j += 32) {
            const int k = cand[wid][j];
            const float* cr = cb + (size_t)k * 256;
            float s = 0.0f;
            for (int d = 0; d < 256; d += 8) {
                float4 c0 = __ldg((const float4*)(cr + d));
                float4 c1 = __ldg((const float4*)(cr + d + 4));
                s = __fmaf_rn(xbuf[wid][d],     c0.x, s);
                s = __fmaf_rn(xbuf[wid][d + 1], c0.y, s);
                s = __fmaf_rn(xbuf[wid][d + 2], c0.z, s);
                s = __fmaf_rn(xbuf[wid][d + 3], c0.w, s);
                s = __fmaf_rn(xbuf[wid][d + 4], c1.x, s);
                s = __fmaf_rn(xbuf[wid][d + 5], c1.y, s);
                s = __fmaf_rn(xbuf[wid][d + 6], c1.z, s);
                s = __fmaf_rn(xbuf[wid][d + 7], c1.w, s);
            }
            float v = __fsub_rn(__fadd_rn(sx, g_cnorm[k]), __fmul_rn(2.0f, s));
            if (v < bv || (v == bv && k < bk)) { bv = v; bk = k; }
        }
#pragma unroll
        for (int s = 16; s >= 1; s >>= 1) {
            float v2 = __shfl_xor_sync(FULL, bv, s);
            int   k2 = __shfl_xor_sync(FULL, bk, s);
            if (v2 < bv || (v2 == bv && k2 < bk)) { bv = v2; bk = k2; }
        }
        if (lane == 0) {
            g_idx[p] = bk;
            out_idx_f[p] = (float)bk;
        }
        __syncwarp();
    }
}

// ---------------------------------------------------------------------------
// Scatter: 64-t tiles (3 CTAs/SM), gather + quantized out + loss.
// ---------------------------------------------------------------------------
__global__ __launch_bounds__(256)
void vq_scatter_kernel(const float* __restrict__ in,
                       const float* __restrict__ cb,
                       float* __restrict__ out_q,
                       float* __restrict__ out_loss) {
    extern __shared__ float sm[];
    float*  q_s  = sm;                           // [64][257]
    double* rsum = (double*)(sm + STT * 257);
    __shared__ int idx_s[STT];

    const int tid = threadIdx.x;
    const int b   = blockIdx.x >> 5;
    const int t0  = (blockIdx.x & 31) * STT;

    if (tid < STT) idx_s[tid] = g_idx[b * T_ + t0 + tid];
    __syncthreads();

    for (int i = tid; i < STT * C_; i += 256) {
        int r = i >> 8, c = i & 255;
        q_s[r * 257 + c] = __ldg(cb + (size_t)idx_s[r] * C_ + c);
    }
    __syncthreads();

    double lsum = 0.0;
    for (int i = tid; i < STT * C_; i += 256) {
        int cc = i >> 6, t = i & 63;
        size_t off = ((size_t)b * C_ + cc) * T_ + t0 + t;
        float q  = q_s[t * 257 + cc];
        float xv = in[off];
        out_q[off] = q;
        float d = __fsub_rn(q, xv);
        lsum += (double)(__fmul_rn(d, d));
    }

    rsum[tid] = lsum;
    __syncthreads();
    for (int s = 128; s > 0; s >>= 1) {
        if (tid < s) rsum[tid] += rsum[tid + s];
        __syncthreads();
    }
    if (tid == 0) {
        atomicAdd(&g_sum, rsum[0]);
        __threadfence();
        int done = atomicAdd(&g_done, 1);
        if (done == gridDim.x - 1) {
            double tot = atomicAdd(&g_sum, 0.0);
            out_loss[0] = (float)(1.25 * tot / (double)OUTQ_ELEMS);
        }
    }
}

// ---------------------------------------------------------------------------
extern "C" void kernel_launch(void* const* d_in, const int* in_sizes, int n_in,
                              void* d_out, int out_size) {
    const float* in = (const float*)d_in[0];
    const float* cb = (const float*)d_in[1];
    if (n_in >= 2 && in_sizes[0] == K_ * C_) {
        const float* t = in; in = cb; cb = t;
    }

    float* out      = (float*)d_out;
    float* out_q    = out;
    float* out_loss = out + OUTQ_ELEMS;
    float* out_idx  = out_loss + 1;

    const int SMEM_PA = 64 * 260 * 4;                     // 66560
    const int SMEM_SC = STT * 257 * 4 + 256 * 8;          // 67840
    cudaFuncSetAttribute(vq_prep_all,
                         cudaFuncAttributeMaxDynamicSharedMemorySize, SMEM_PA);
    cudaFuncSetAttribute(vq_gemm_kernel,
                         cudaFuncAttributeMaxDynamicSharedMemorySize, SMEM_G);
    cudaFuncSetAttribute(vq_scatter_kernel,
                         cudaFuncAttributeMaxDynamicSharedMemorySize, SMEM_SC);

    vq_prep_all<<<528, 256, SMEM_PA>>>(in, cb);   // 1
    vq_gemm_kernel<<<2048, 512, SMEM_G>>>();      // 2
    vq_classify_kernel<<<256, 256>>>(out_idx);    // 3
    vq_refine_kernel<<<512, RW * 32>>>(cb, out_idx);           // 4 -> profiled
    vq_scatter_kernel<<<1024, 256, SMEM_SC>>>(in, cb, out_q, out_loss); // 5
}

// round 15
// speedup vs baseline: 1.7814x; 1.7814x over previous
#include <cuda_runtime.h>
#include <cuda_fp16.h>

#define B_  32
#define C_  256
#define T_  2048
#define K_  1024
#define N_  (B_ * T_)        // 65536
#define STT 64
#define OUTQ_ELEMS ((size_t)B_ * C_ * T_)

#define EPS 1.6e-3f
#define TWO_POW_M9 0.001953125f   // exact 2^-9

// device scratch (static — no allocation)
__device__ float    g_cnorm[K_];
__device__ float    g_sx[N_];
__device__ __half   g_A[(size_t)N_ * 256];    // x0 = rn16(x), 32MB
__device__ float    g_xr[(size_t)N_ * 256];   // exact fp32 x rows, 64MB
__device__ __half   g_B[(size_t)K_ * 256];    // c0 = rn16(c * 2^10)
__device__ float    g_tbv[4 * N_];            // per-(ntile, point) approx best
__device__ unsigned g_mask[(size_t)4 * N_ * 8]; // 256-bit candidate masks
__device__ int      g_idx[N_];
__device__ int      g_queue[N_];
__device__ int      g_nq;
__device__ int      g_qhead;
__device__ int      g_done;
__device__ double   g_sum;

// ---------------- helpers ----------------
__device__ __forceinline__ unsigned smem_u32(const void* p) {
    unsigned r;
    asm("{ .reg .u64 t; cvta.to.shared.u64 t, %1; cvt.u32.u64 %0, t; }"
        : "=r"(r) : "l"(p));
    return r;
}
__device__ __forceinline__ void cp16(unsigned dst, const void* src) {
    asm volatile("cp.async.cg.shared.global [%0], [%1], 16;" :: "r"(dst), "l"(src));
}
__device__ __forceinline__ void mma16816(float* d, const unsigned* a, const unsigned* b) {
    asm volatile("mma.sync.aligned.m16n8k16.row.col.f32.f16.f16.f32 "
        "{%0,%1,%2,%3}, {%4,%5,%6,%7}, {%8,%9}, {%0,%1,%2,%3};"
        : "+f"(d[0]), "+f"(d[1]), "+f"(d[2]), "+f"(d[3])
        : "r"(a[0]), "r"(a[1]), "r"(a[2]), "r"(a[3]), "r"(b[0]), "r"(b[1]));
}

// ---------------------------------------------------------------------------
// Prep CB (+ scalar init): 16 blocks, smem-staged coalesced, exact chain.
// ---------------------------------------------------------------------------
__global__ __launch_bounds__(256)
void vq_prep_cb(const float* __restrict__ cb) {
    extern __shared__ float tile[];    // 64 * 260 floats
    const int tid = threadIdx.x;
    const int k0  = blockIdx.x * 64;
    if (blockIdx.x == 0 && tid == 0) {
        g_sum = 0.0; g_nq = 0; g_qhead = 0; g_done = 0;
    }

    for (int i = tid; i < 4096; i += 256) {
        int row = i >> 6, c4 = i & 63;
        *(float4*)&tile[row * 260 + c4 * 4] =
            __ldg((const float4*)(cb + (size_t)(k0 + row) * 256) + c4);
    }
    __syncthreads();

    if (tid < 64) {
        const float* r = &tile[tid * 260];
        float s = 0.0f;
        for (int d = 0; d < 256; ++d)
            s = __fadd_rn(s, __fmul_rn(r[d], r[d]));
        g_cnorm[k0 + tid] = s;
    }

    for (int i = tid; i < 2048; i += 256) {
        int row = i >> 5, g = i & 31;
        const float* src = &tile[row * 260 + g * 8];
        __half h[8];
#pragma unroll
        for (int j = 0; j < 8; ++j) h[j] = __float2half_rn(src[j] * 1024.0f);
        *(uint4*)(g_B + (size_t)(k0 + row) * 256 + g * 8) = *(uint4*)h;
    }
}

// ---------------------------------------------------------------------------
// Prep X: static 34KB smem (6 CTAs/SM), bulk float4 loads, exact sx chain.
// ---------------------------------------------------------------------------
__global__ __launch_bounds__(256)
void vq_prep_x(const float* __restrict__ in) {
    __shared__ float tile[64 * 132];
    const int tid = threadIdx.x;
    const int b = blockIdx.x >> 4, t0 = (blockIdx.x & 15) * 128;
    float s = 0.0f;

    for (int ch = 0; ch < 4; ++ch) {
        for (int i = tid; i < 2048; i += 256) {
            int d = i >> 5, q = i & 31;
            float4 v = __ldg((const float4*)(
                in + ((size_t)b * C_ + ch * 64 + d) * T_ + t0 + q * 4));
            *(float4*)&tile[d * 132 + q * 4] = v;
        }
        __syncthreads();

        if (tid < 128) {
#pragma unroll 8
            for (int dl = 0; dl < 64; ++dl) {
                float v = tile[dl * 132 + tid];
                s = __fadd_rn(s, __fmul_rn(v, v));
            }
        }

        for (int i = tid; i < 2048; i += 256) {
            int row = i >> 4, g = i & 15;
            float f0 = tile[(g * 4 + 0) * 132 + row];
            float f1 = tile[(g * 4 + 1) * 132 + row];
            float f2 = tile[(g * 4 + 2) * 132 + row];
            float f3 = tile[(g * 4 + 3) * 132 + row];
            const size_t p = (size_t)b * T_ + t0 + row;
            *(float4*)(g_xr + p * 256 + ch * 64 + g * 4) =
                make_float4(f0, f1, f2, f3);
            __half h[4] = { __float2half_rn(f0), __float2half_rn(f1),
                            __float2half_rn(f2), __float2half_rn(f3) };
            *(uint2*)(g_A + p * 256 + ch * 64 + g * 4) = *(uint2*)h;
        }
        __syncthreads();
    }
    if (tid < 128) g_sx[(size_t)b * T_ + t0 + tid] = s;
}

// ---------------------------------------------------------------------------
// GEMM + candidate-mask. 128t x 256n x K256, 256 thr / 8 warps, 64x64 tiles,
// 3-stage pipeline. (Best measured: 121 us — frozen.)
// ---------------------------------------------------------------------------
#define SMEM_AS 0          // 3 x 16384
#define SMEM_BS 49152      // 3 x 32768 -> ends 147456
#define SMEM_CN 147456
#define SMEM_SX 148480
#define SMEM_RV 148992     // [128][4] float
#define SMEM_MK 151040     // [128][8] u32
#define SMEM_BT 155136
#define SMEM_G  155648

__device__ __forceinline__ void load_chunk(unsigned as0, unsigned bs0, int stage,
                                           size_t aRowBase, int n0, int c, int tid) {
    unsigned abase = as0 + stage * 16384;
    const __half* asrc = g_A + aRowBase + c * 64;
    for (int i = tid; i < 1024; i += 256) {
        int r = i >> 3, g = i & 7;
        cp16(abase + r * 128 + ((g ^ (r & 7)) << 4), asrc + (size_t)r * 256 + g * 8);
    }
    unsigned bbase = bs0 + stage * 32768;
    const __half* bsrc = g_B + (size_t)n0 * 256 + c * 64;
    for (int i = tid; i < 2048; i += 256) {
        int r = i >> 3, g = i & 7;
        cp16(bbase + r * 128 + ((g ^ (r & 7)) << 4), bsrc + (size_t)r * 256 + g * 8);
    }
}

__global__ __launch_bounds__(256, 1)
void vq_gemm_kernel() {
    extern __shared__ char smem[];
    unsigned sb  = smem_u32(smem);
    unsigned as0 = sb + SMEM_AS, bs0 = sb + SMEM_BS;
    float*    cn_s   = (float*)(smem + SMEM_CN);
    float*    sx_s   = (float*)(smem + SMEM_SX);
    float*    red_v  = (float*)(smem + SMEM_RV);
    unsigned* mask_s = (unsigned*)(smem + SMEM_MK);
    float*    best_s = (float*)(smem + SMEM_BT);

    const int tid  = threadIdx.x;
    const int lane = tid & 31, wid = tid >> 5;
    const int wm = wid >> 2, wn = wid & 3;
    const int tTile = blockIdx.x >> 2, nTile = blockIdx.x & 3;
    const int gt0 = tTile * 128, n0 = nTile * 256;
    const size_t aRowBase = (size_t)gt0 * 256;

    load_chunk(as0, bs0, 0, aRowBase, n0, 0, tid);
    asm volatile("cp.async.commit_group;");
    load_chunk(as0, bs0, 1, aRowBase, n0, 1, tid);
    asm volatile("cp.async.commit_group;");

    if (tid < 128) sx_s[tid] = g_sx[gt0 + tid];
    cn_s[tid] = g_cnorm[n0 + tid];

    float acc[4][8][4];
#pragma unroll
    for (int m = 0; m < 4; ++m)
#pragma unroll
        for (int n = 0; n < 8; ++n)
#pragma unroll
            for (int j = 0; j < 4; ++j) acc[m][n][j] = 0.0f;

#pragma unroll
    for (int c = 0; c < 4; ++c) {
        if (c < 3) { asm volatile("cp.async.wait_group 1;"); }
        else       { asm volatile("cp.async.wait_group 0;"); }
        __syncthreads();
        const int stage = c % 3;
        const unsigned abase = as0 + stage * 16384;
        const unsigned bbase = bs0 + stage * 32768;

#pragma unroll
        for (int kk = 0; kk < 4; ++kk) {
            unsigned a_frag[4][4], b_frag[8][2];
#pragma unroll
            for (int m = 0; m < 4; ++m) {
                int trow = wm * 64 + m * 16 + (lane & 15);
                int g = (kk << 1) + (lane >> 4);
                unsigned addr = abase + trow * 128 + ((g ^ (lane & 7)) << 4);
                asm volatile("ldmatrix.sync.aligned.m8n8.x4.shared.b16 {%0,%1,%2,%3}, [%4];"
                    : "=r"(a_frag[m][0]), "=r"(a_frag[m][1]),
                      "=r"(a_frag[m][2]), "=r"(a_frag[m][3]) : "r"(addr));
            }
#pragma unroll
            for (int n2 = 0; n2 < 4; ++n2) {
                int nrow = wn * 64 + n2 * 16 + ((lane >> 4) & 1) * 8 + (lane & 7);
                int g = (kk << 1) + ((lane >> 3) & 1);
                unsigned addr = bbase + nrow * 128 + ((g ^ (lane & 7)) << 4);
                asm volatile("ldmatrix.sync.aligned.m8n8.x4.shared.b16 {%0,%1,%2,%3}, [%4];"
                    : "=r"(b_frag[n2 * 2][0]),     "=r"(b_frag[n2 * 2][1]),
                      "=r"(b_frag[n2 * 2 + 1][0]), "=r"(b_frag[n2 * 2 + 1][1])
                    : "r"(addr));
            }
#pragma unroll
            for (int m = 0; m < 4; ++m)
#pragma unroll
                for (int n = 0; n < 8; ++n)
                    mma16816(acc[m][n], a_frag[m], b_frag[n]);
        }

        if (c + 2 < 4) {
            load_chunk(as0, bs0, (c + 2) % 3, aRowBase, n0, c + 2, tid);
            asm volatile("cp.async.commit_group;");
        }
    }

    // Pass 1: per-t tile-best
#pragma unroll
    for (int m = 0; m < 4; ++m) {
        const int ra = wm * 64 + m * 16 + (lane >> 2);
        const int rb = ra + 8;
        const float sxa = sx_s[ra], sxb = sx_s[rb];
        float va = 3.4e38f, vb = 3.4e38f;
#pragma unroll
        for (int n = 0; n < 8; ++n) {
            const int kc = wn * 64 + n * 8 + ((lane & 3) << 1);
            const float sc0 = cn_s[kc], sc1 = cn_s[kc + 1];
            const float* d = acc[m][n];
            va = fminf(va, __fsub_rn(__fadd_rn(sxa, sc0), __fmul_rn(d[0], TWO_POW_M9)));
            va = fminf(va, __fsub_rn(__fadd_rn(sxa, sc1), __fmul_rn(d[1], TWO_POW_M9)));
            vb = fminf(vb, __fsub_rn(__fadd_rn(sxb, sc0), __fmul_rn(d[2], TWO_POW_M9)));
            vb = fminf(vb, __fsub_rn(__fadd_rn(sxb, sc1), __fmul_rn(d[3], TWO_POW_M9)));
        }
#pragma unroll
        for (int s = 1; s <= 2; s <<= 1) {
            va = fminf(va, __shfl_xor_sync(0xffffffffu, va, s));
            vb = fminf(vb, __shfl_xor_sync(0xffffffffu, vb, s));
        }
        if ((lane & 3) == 0) {
            red_v[ra * 4 + wn] = va;
            red_v[rb * 4 + wn] = vb;
        }
    }
    __syncthreads();
    if (tid < 128) {
        float bv = red_v[tid * 4];
#pragma unroll
        for (int w = 1; w < 4; ++w) bv = fminf(bv, red_v[tid * 4 + w]);
        best_s[tid] = bv;
    }
    __syncthreads();

    // Pass 2: candidate bits (warp wn owns words wn*2, wn*2+1)
#pragma unroll
    for (int m = 0; m < 4; ++m) {
        const int ra = wm * 64 + m * 16 + (lane >> 2);
        const int rb = ra + 8;
        const float sxa = sx_s[ra], sxb = sx_s[rb];
        const float tha = best_s[ra] + EPS, thb = best_s[rb] + EPS;
        unsigned lma[2] = {0u, 0u}, lmb[2] = {0u, 0u};
#pragma unroll
        for (int n = 0; n < 8; ++n) {
            const int w = n >> 2;
            const int bitp = (n & 3) * 8 + ((lane & 3) << 1);
            const int kc = wn * 64 + n * 8 + ((lane & 3) << 1);
            const float sc0 = cn_s[kc], sc1 = cn_s[kc + 1];
            const float* d = acc[m][n];
            if (__fsub_rn(__fadd_rn(sxa, sc0), __fmul_rn(d[0], TWO_POW_M9)) <= tha)
                lma[w] |= 1u << bitp;
            if (__fsub_rn(__fadd_rn(sxa, sc1), __fmul_rn(d[1], TWO_POW_M9)) <= tha)
                lma[w] |= 1u << (bitp + 1);
            if (__fsub_rn(__fadd_rn(sxb, sc0), __fmul_rn(d[2], TWO_POW_M9)) <= thb)
                lmb[w] |= 1u << bitp;
            if (__fsub_rn(__fadd_rn(sxb, sc1), __fmul_rn(d[3], TWO_POW_M9)) <= thb)
                lmb[w] |= 1u << (bitp + 1);
        }
#pragma unroll
        for (int w = 0; w < 2; ++w) {
            lma[w] |= __shfl_xor_sync(0xffffffffu, lma[w], 1);
            lma[w] |= __shfl_xor_sync(0xffffffffu, lma[w], 2);
            lmb[w] |= __shfl_xor_sync(0xffffffffu, lmb[w], 1);
            lmb[w] |= __shfl_xor_sync(0xffffffffu, lmb[w], 2);
        }
        if ((lane & 3) == 0) {
#pragma unroll
            for (int w = 0; w < 2; ++w) {
                mask_s[ra * 8 + wn * 2 + w] = lma[w];
                mask_s[rb * 8 + wn * 2 + w] = lmb[w];
            }
        }
    }
    __syncthreads();

    if (tid < 128) g_tbv[nTile * N_ + gt0 + tid] = best_s[tid];
    for (int i = tid; i < 1024; i += 256) {
        int t = i >> 3, w = i & 7;
        g_mask[((size_t)nTile * N_ + gt0 + t) * 8 + w] = mask_s[t * 8 + w];
    }
}

// ---------------------------------------------------------------------------
// Classify: single-candidate points resolved inline; rest -> global queue.
// ---------------------------------------------------------------------------
__global__ __launch_bounds__(256)
void vq_classify_kernel(float* __restrict__ out_idx_f) {
    const int p = blockIdx.x * 256 + threadIdx.x;
    float tb0 = g_tbv[p],           tb1 = g_tbv[N_ + p];
    float tb2 = g_tbv[2 * N_ + p],  tb3 = g_tbv[3 * N_ + p];
    const float thr = fminf(fminf(tb0, tb1), fminf(tb2, tb3)) + EPS;

    int nc = 0, firstk = -1;
#pragma unroll
    for (int i = 0; i < 4; ++i) {
        float tbi = (i == 0) ? tb0 : (i == 1) ? tb1 : (i == 2) ? tb2 : tb3;
        if (tbi <= thr) {
#pragma unroll
            for (int w = 0; w < 8; ++w) {
                unsigned m = g_mask[((size_t)i * N_ + p) * 8 + w];
                if (m) {
                    if (firstk < 0) firstk = i * 256 + w * 32 + (__ffs(m) - 1);
                    nc += __popc(m);
                }
            }
        }
    }
    if (nc == 1) {
        g_idx[p] = firstk;
        out_idx_f[p] = (float)firstk;
    } else {
        int pos = atomicAdd(&g_nq, 1);
        g_queue[pos] = p;
    }
}

// ---------------------------------------------------------------------------
// Exact refine: one warp per queued point, global work-stealing queue.
// ---------------------------------------------------------------------------
#define RW 8
__global__ __launch_bounds__(RW * 32)
void vq_refine_kernel(const float* __restrict__ cb,
                      float* __restrict__ out_idx_f) {
    __shared__ float xbuf[RW][256];
    __shared__ int   cand[RW][128];
    __shared__ int   qpos[RW];

    const int lane = threadIdx.x & 31;
    const int wid  = threadIdx.x >> 5;
    const unsigned FULL = 0xffffffffu;
    const int total = g_nq;

    for (;;) {
        if (lane == 0) qpos[wid] = atomicAdd(&g_qhead, 1);
        __syncwarp();
        const int qp = qpos[wid];
        if (qp >= total) break;
        const int p = g_queue[qp];

        float tbl = (lane < 4) ? g_tbv[lane * N_ + p] : 3.4e38f;
        float gb = tbl;
#pragma unroll
        for (int s = 1; s < 4; s <<= 1)
            gb = fminf(gb, __shfl_xor_sync(FULL, gb, s));
        gb = __shfl_sync(FULL, gb, 0);
        const float thr = gb + EPS;

        const int ti = lane >> 3;
        float tbi = __shfl_sync(FULL, tbl, ti);
        unsigned m = 0;
        if (tbi <= thr) m = g_mask[((size_t)ti * N_ + p) * 8 + (lane & 7)];
        int cnt = __popc(m);
        int pre = cnt;
#pragma unroll
        for (int s = 1; s < 32; s <<= 1) {
            int v = __shfl_up_sync(FULL, pre, s);
            if (lane >= s) pre += v;
        }
        int nc = __shfl_sync(FULL, pre, 31);
        if (nc > 128) nc = 128;
        int excl = pre - cnt;
        unsigned mm = m;
        while (mm && excl < 128) {
            int bpos = __ffs(mm) - 1;
            mm &= mm - 1;
            cand[wid][excl++] = lane * 32 + bpos;
        }

        {
            const float4* src = (const float4*)(g_xr + (size_t)p * 256);
            float4* dst = (float4*)xbuf[wid];
            dst[lane]      = src[lane];
            dst[lane + 32] = src[lane + 32];
        }
        __syncwarp();

        const float sx = g_sx[p];
        float bv = 3.4e38f;
        int   bk = 0x7fffffff;
        for (int j = lane; j < nc; j += 32) {
            const int k = cand[wid][j];
            const float* cr = cb + (size_t)k * 256;
            float s = 0.0f;
            for (int d = 0; d < 256; d += 8) {
                float4 c0 = __ldg((const float4*)(cr + d));
                float4 c1 = __ldg((const float4*)(cr + d + 4));
                s = __fmaf_rn(xbuf[wid][d],     c0.x, s);
                s = __fmaf_rn(xbuf[wid][d + 1], c0.y, s);
                s = __fmaf_rn(xbuf[wid][d + 2], c0.z, s);
                s = __fmaf_rn(xbuf[wid][d + 3], c0.w, s);
                s = __fmaf_rn(xbuf[wid][d + 4], c1.x, s);
                s = __fmaf_rn(xbuf[wid][d + 5], c1.y, s);
                s = __fmaf_rn(xbuf[wid][d + 6], c1.z, s);
                s = __fmaf_rn(xbuf[wid][d + 7], c1.w, s);
            }
            float v = __fsub_rn(__fadd_rn(sx, g_cnorm[k]), __fmul_rn(2.0f, s));
            if (v < bv || (v == bv && k < bk)) { bv = v; bk = k; }
        }
#pragma unroll
        for (int s = 16; s >= 1; s >>= 1) {
            float v2 = __shfl_xor_sync(FULL, bv, s);
            int   k2 = __shfl_xor_sync(FULL, bk, s);
            if (v2 < bv || (v2 == bv && k2 < bk)) { bv = v2; bk = k2; }
        }
        if (lane == 0) {
            g_idx[p] = bk;
            out_idx_f[p] = (float)bk;
        }
        __syncwarp();
    }
}

// ---------------------------------------------------------------------------
// Scatter: 64-t tiles (3 CTAs/SM), gather + quantized out + loss.
// ---------------------------------------------------------------------------
__global__ __launch_bounds__(256)
void vq_scatter_kernel(const float* __restrict__ in,
                       const float* __restrict__ cb,
                       float* __restrict__ out_q,
                       float* __restrict__ out_loss) {
    extern __shared__ float sm[];
    float*  q_s  = sm;                           // [64][257]
    double* rsum = (double*)(sm + STT * 257);
    __shared__ int idx_s[STT];

    const int tid = threadIdx.x;
    const int b   = blockIdx.x >> 5;
    const int t0  = (blockIdx.x & 31) * STT;

    if (tid < STT) idx_s[tid] = g_idx[b * T_ + t0 + tid];
    __syncthreads();

    for (int i = tid; i < STT * C_; i += 256) {
        int r = i >> 8, c = i & 255;
        q_s[r * 257 + c] = __ldg(cb + (size_t)idx_s[r] * C_ + c);
    }
    __syncthreads();

    double lsum = 0.0;
    for (int i = tid; i < STT * C_; i += 256) {
        int cc = i >> 6, t = i & 63;
        size_t off = ((size_t)b * C_ + cc) * T_ + t0 + t;
        float q  = q_s[t * 257 + cc];
        float xv = in[off];
        out_q[off] = q;
        float d = __fsub_rn(q, xv);
        lsum += (double)(__fmul_rn(d, d));
    }

    rsum[tid] = lsum;
    __syncthreads();
    for (int s = 128; s > 0; s >>= 1) {
        if (tid < s) rsum[tid] += rsum[tid + s];
        __syncthreads();
    }
    if (tid == 0) {
        atomicAdd(&g_sum, rsum[0]);
        __threadfence();
        int done = atomicAdd(&g_done, 1);
        if (done == gridDim.x - 1) {
            double tot = atomicAdd(&g_sum, 0.0);
            out_loss[0] = (float)(1.25 * tot / (double)OUTQ_ELEMS);
        }
    }
}

// ---------------------------------------------------------------------------
extern "C" void kernel_launch(void* const* d_in, const int* in_sizes, int n_in,
                              void* d_out, int out_size) {
    const float* in = (const float*)d_in[0];
    const float* cb = (const float*)d_in[1];
    if (n_in >= 2 && in_sizes[0] == K_ * C_) {
        const float* t = in; in = cb; cb = t;
    }

    float* out      = (float*)d_out;
    float* out_q    = out;
    float* out_loss = out + OUTQ_ELEMS;
    float* out_idx  = out_loss + 1;

    const int SMEM_PC = 64 * 260 * 4;                     // 66560
    const int SMEM_SC = STT * 257 * 4 + 256 * 8;          // 67840
    cudaFuncSetAttribute(vq_prep_cb,
                         cudaFuncAttributeMaxDynamicSharedMemorySize, SMEM_PC);
    cudaFuncSetAttribute(vq_gemm_kernel,
                         cudaFuncAttributeMaxDynamicSharedMemorySize, SMEM_G);
    cudaFuncSetAttribute(vq_scatter_kernel,
                         cudaFuncAttributeMaxDynamicSharedMemorySize, SMEM_SC);

    vq_prep_cb<<<16, 256, SMEM_PC>>>(cb);         // 1
    vq_prep_x<<<512, 256>>>(in);                  // 2
    vq_gemm_kernel<<<2048, 256, SMEM_G>>>();      // 3
    vq_classify_kernel<<<256, 256>>>(out_idx);    // 4 -> profiled
    vq_refine_kernel<<<512, RW * 32>>>(cb, out_idx);           // 5
    vq_scatter_kernel<<<1024, 256, SMEM_SC>>>(in, cb, out_q, out_loss); // 6
}